// round 1
// baseline (speedup 1.0000x reference)
#include <cuda_runtime.h>
#include <float.h>

#define NPIX 65536
#define FDIM 224
#define PDIM 6
#define HDIM 256

// Scratch (static device memory — no allocation allowed)
__device__ float g_h1[NPIX * HDIM];
__device__ float g_h2[NPIX * HDIM];
__device__ float g_logits[NPIX * FDIM];
__device__ int   g_cls[NPIX];
__device__ float g_M[PDIM * FDIM];

// ---------------------------------------------------------------------------
// argmax over P=6 abundances per pixel (first-max wins, matching jnp.argmax)
// ---------------------------------------------------------------------------
__global__ void cls_kernel(const float* __restrict__ ab, int* __restrict__ cls) {
    int i = blockIdx.x * 256 + threadIdx.x;
    if (i >= NPIX) return;
    float bv = ab[i * PDIM];
    int best = 0;
#pragma unroll
    for (int p = 1; p < PDIM; p++) {
        float v = ab[i * PDIM + p];
        if (v > bv) { bv = v; best = p; }
    }
    cls[i] = best;
}

// ---------------------------------------------------------------------------
// SGEMM with fused bias (+optional ReLU): C[M,N] = act(A[M,K] @ B[K,N] + bias)
// 128x128 block tile, BK=8, 256 threads, 8x8 per thread.
// M assumed multiple of 128, K multiple of 8, N multiple of 4 (col-guarded).
// ---------------------------------------------------------------------------
template <bool RELU>
__global__ __launch_bounds__(256, 2) void sgemm_bias(
    const float* __restrict__ A, const float* __restrict__ B,
    const float* __restrict__ bias, float* __restrict__ C,
    int M, int N, int K)
{
    constexpr int BM = 128, BN = 128, BK = 8;
    __shared__ float As[BK][BM];
    __shared__ float Bs[BK][BN];

    const int t  = threadIdx.x;
    const int tx = t & 15;     // 0..15 -> output col group
    const int ty = t >> 4;     // 0..15 -> output row group
    const int brow = blockIdx.y;
    const int bcol = blockIdx.x;

    float acc[8][8];
#pragma unroll
    for (int i = 0; i < 8; i++)
#pragma unroll
        for (int j = 0; j < 8; j++) acc[i][j] = 0.0f;

    // A-tile load mapping: thread t loads float4 of row (t/2), k-offset (t&1)*4
    const int aRowL = t >> 1;                 // 0..127
    const int aK    = (t & 1) * 4;            // 0 or 4
    const float* Ap = A + (brow * BM + aRowL) * (long)K + aK;

    // B-tile load mapping: thread t loads float4 of k-row (t/32), col (t&31)*4
    const int bK    = t >> 5;                 // 0..7
    const int bColL = (t & 31) * 4;           // 0..124
    const int bCol  = bcol * BN + bColL;
    const bool bOk  = (bCol < N);
    const float* Bp = B + (long)bK * N + bCol;

    for (int k0 = 0; k0 < K; k0 += BK) {
        float4 av = *reinterpret_cast<const float4*>(Ap + k0);
        As[aK + 0][aRowL] = av.x;
        As[aK + 1][aRowL] = av.y;
        As[aK + 2][aRowL] = av.z;
        As[aK + 3][aRowL] = av.w;

        float4 bv = make_float4(0.f, 0.f, 0.f, 0.f);
        if (bOk) bv = *reinterpret_cast<const float4*>(Bp + (long)k0 * N);
        *reinterpret_cast<float4*>(&Bs[bK][bColL]) = bv;

        __syncthreads();

#pragma unroll
        for (int k = 0; k < BK; k++) {
            float ar[8], br[8];
            *reinterpret_cast<float4*>(&ar[0]) = *reinterpret_cast<const float4*>(&As[k][ty * 8]);
            *reinterpret_cast<float4*>(&ar[4]) = *reinterpret_cast<const float4*>(&As[k][ty * 8 + 4]);
            *reinterpret_cast<float4*>(&br[0]) = *reinterpret_cast<const float4*>(&Bs[k][tx * 8]);
            *reinterpret_cast<float4*>(&br[4]) = *reinterpret_cast<const float4*>(&Bs[k][tx * 8 + 4]);
#pragma unroll
            for (int i = 0; i < 8; i++)
#pragma unroll
                for (int j = 0; j < 8; j++)
                    acc[i][j] += ar[i] * br[j];
        }
        __syncthreads();
    }

    const int row0 = brow * BM + ty * 8;
    const int col0 = bcol * BN + tx * 8;
#pragma unroll
    for (int i = 0; i < 8; i++) {
#pragma unroll
        for (int j = 0; j < 8; j++) {
            int col = col0 + j;
            if (col < N) {
                float v = acc[i][j] + bias[col];
                if (RELU) v = fmaxf(v, 0.0f);
                C[(long)(row0 + i) * N + col] = v;
            }
        }
    }
}

// ---------------------------------------------------------------------------
// Per-class masked softmax over pixels, per feature column.
// One block per feature f. Each thread: online softmax stats for 6 classes.
// Deterministic tree reduction in shared memory.
// M[p,f] = sum_n(in class p) softmax_w(logits[n,f]) * Y[n,f]
// ---------------------------------------------------------------------------
__global__ __launch_bounds__(256) void endmember_kernel(
    const float* __restrict__ logits, const float* __restrict__ Y,
    const int* __restrict__ cls, float* __restrict__ Mo)
{
    const int f = blockIdx.x;
    const int t = threadIdx.x;

    float m[PDIM], s[PDIM], sy[PDIM];
#pragma unroll
    for (int p = 0; p < PDIM; p++) { m[p] = -FLT_MAX; s[p] = 0.f; sy[p] = 0.f; }

    for (int n = t; n < NPIX; n += 256) {
        const int c = cls[n];
        const float l = logits[(long)n * FDIM + f];
        const float y = Y[(long)n * FDIM + f];

        // gather stats for class c (branchless, keeps arrays in registers)
        float mc = m[0], sc = s[0], syc = sy[0];
#pragma unroll
        for (int p = 1; p < PDIM; p++) {
            bool e = (c == p);
            mc = e ? m[p] : mc;
            sc = e ? s[p] : sc;
            syc = e ? sy[p] : syc;
        }
        float mn  = fmaxf(mc, l);
        float sca = __expf(mc - mn);   // -> 0 when mc == -FLT_MAX
        float ea  = __expf(l - mn);
        float sn  = sc * sca + ea;
        float syn = syc * sca + ea * y;
#pragma unroll
        for (int p = 0; p < PDIM; p++) {
            bool e = (c == p);
            m[p]  = e ? mn  : m[p];
            s[p]  = e ? sn  : s[p];
            sy[p] = e ? syn : sy[p];
        }
    }

    __shared__ float sm[PDIM][256];
    __shared__ float ss[PDIM][256];
    __shared__ float ssy[PDIM][256];
#pragma unroll
    for (int p = 0; p < PDIM; p++) { sm[p][t] = m[p]; ss[p][t] = s[p]; ssy[p][t] = sy[p]; }
    __syncthreads();

    for (int off = 128; off > 0; off >>= 1) {
        if (t < off) {
#pragma unroll
            for (int p = 0; p < PDIM; p++) {
                float mA = sm[p][t],        sA = ss[p][t],        syA = ssy[p][t];
                float mB = sm[p][t + off],  sB = ss[p][t + off],  syB = ssy[p][t + off];
                float mx = fmaxf(mA, mB);
                float eA = __expf(mA - mx);  // both -FLT_MAX -> exp(0)=1 * s=0 -> 0, ok
                float eB = __expf(mB - mx);
                sm[p][t]  = mx;
                ss[p][t]  = sA * eA + sB * eB;
                ssy[p][t] = syA * eA + syB * eB;
            }
        }
        __syncthreads();
    }

    if (t == 0) {
#pragma unroll
        for (int p = 0; p < PDIM; p++) {
            float S = ss[p][0];
            Mo[p * FDIM + f] = (S > 0.f) ? (ssy[p][0] / S) : 0.0f;
        }
    }
}

// ---------------------------------------------------------------------------
// Y_hat[n,f] = sum_p abundance[n,p] * M[p,f]
// ---------------------------------------------------------------------------
__global__ __launch_bounds__(256) void yhat_kernel(
    const float* __restrict__ ab, const float* __restrict__ M,
    float* __restrict__ out)
{
    __shared__ float sM[PDIM * FDIM];
    for (int i = threadIdx.x; i < PDIM * FDIM; i += 256) sM[i] = M[i];
    __syncthreads();

    long idx = (long)blockIdx.x * 256 + threadIdx.x;
    if (idx >= (long)NPIX * FDIM) return;
    int n = (int)(idx / FDIM);
    int f = (int)(idx % FDIM);
    const float* a = ab + (long)n * PDIM;
    float acc = 0.f;
#pragma unroll
    for (int p = 0; p < PDIM; p++) acc += a[p] * sM[p * FDIM + f];
    out[idx] = acc;
}

// ---------------------------------------------------------------------------
extern "C" void kernel_launch(void* const* d_in, const int* in_sizes, int n_in,
                              void* d_out, int out_size)
{
    const float* ab = (const float*)d_in[0];
    const float* Y  = (const float*)d_in[1];
    const float* W1 = (const float*)d_in[2];
    const float* b1 = (const float*)d_in[3];
    const float* W2 = (const float*)d_in[4];
    const float* b2 = (const float*)d_in[5];
    const float* W3 = (const float*)d_in[6];
    const float* b3 = (const float*)d_in[7];
    float* out = (float*)d_out;

    float *h1, *h2, *lg, *M;
    int* cls;
    cudaGetSymbolAddress((void**)&h1,  g_h1);
    cudaGetSymbolAddress((void**)&h2,  g_h2);
    cudaGetSymbolAddress((void**)&lg,  g_logits);
    cudaGetSymbolAddress((void**)&cls, g_cls);
    cudaGetSymbolAddress((void**)&M,   g_M);

    cls_kernel<<<(NPIX + 255) / 256, 256>>>(ab, cls);

    // h1 = relu(Y @ W1 + b1)   [65536,224]x[224,256]
    sgemm_bias<true><<<dim3((HDIM + 127) / 128, NPIX / 128), 256>>>(
        Y, W1, b1, h1, NPIX, HDIM, FDIM);
    // h2 = relu(h1 @ W2 + b2)  [65536,256]x[256,256]
    sgemm_bias<true><<<dim3((HDIM + 127) / 128, NPIX / 128), 256>>>(
        h1, W2, b2, h2, NPIX, HDIM, HDIM);
    // logits = h2 @ W3 + b3    [65536,256]x[256,224]
    sgemm_bias<false><<<dim3((FDIM + 127) / 128, NPIX / 128), 256>>>(
        h2, W3, b3, lg, NPIX, FDIM, HDIM);

    endmember_kernel<<<FDIM, 256>>>(lg, Y, cls, M);

    yhat_kernel<<<(int)(((long)NPIX * FDIM + 255) / 256), 256>>>(ab, M, out);
}

// round 4
// speedup vs baseline: 1.7206x; 1.7206x over previous
#include <cuda_runtime.h>
#include <cstdint>
#include <float.h>

#define NPIX 65536
#define FDIM 224
#define PDIM 6
#define HDIM 256
#define NSPLIT 8

// ------------------------- static device scratch ---------------------------
__device__ float g_h1[NPIX * HDIM];
__device__ float g_h2[NPIX * HDIM];
__device__ float g_logits[NPIX * FDIM];
__device__ int   g_cls[NPIX];
__device__ float g_M[PDIM * FDIM];
__device__ float g_W1T[HDIM * FDIM];
__device__ float g_W2T[HDIM * HDIM];
__device__ float g_W3T[FDIM * HDIM];
__device__ float g_part[NSPLIT][PDIM][3][FDIM];

// ------------------------------ PTX helpers --------------------------------
__device__ __forceinline__ uint32_t smem_u32(const void* p) {
    uint32_t a;
    asm("{ .reg .u64 t; cvta.to.shared.u64 t, %1; cvt.u32.u64 %0, t; }"
        : "=r"(a) : "l"(p));
    return a;
}
__device__ __forceinline__ void cpa16(uint32_t dst, const void* src, uint32_t sz) {
    asm volatile("cp.async.cg.shared.global [%0], [%1], 16, %2;"
                 :: "r"(dst), "l"(src), "r"(sz) : "memory");
}
__device__ __forceinline__ void cpa_commit() {
    asm volatile("cp.async.commit_group;" ::: "memory");
}
template <int n> __device__ __forceinline__ void cpa_wait() {
    asm volatile("cp.async.wait_group %0;" :: "n"(n) : "memory");
}
__device__ __forceinline__ void ldsm4(uint32_t* r, uint32_t addr) {
    asm volatile("ldmatrix.sync.aligned.m8n8.x4.shared.b16 {%0,%1,%2,%3}, [%4];"
                 : "=r"(r[0]), "=r"(r[1]), "=r"(r[2]), "=r"(r[3]) : "r"(addr));
}
__device__ __forceinline__ void ldsm2(uint32_t* r, uint32_t addr) {
    asm volatile("ldmatrix.sync.aligned.m8n8.x2.shared.b16 {%0,%1}, [%2];"
                 : "=r"(r[0]), "=r"(r[1]) : "r"(addr));
}
__device__ __forceinline__ void mma_tf32(float* d, const uint32_t* a, const uint32_t* b) {
    asm volatile(
        "mma.sync.aligned.m16n8k8.row.col.f32.tf32.tf32.f32 "
        "{%0,%1,%2,%3}, {%4,%5,%6,%7}, {%8,%9}, {%0,%1,%2,%3};"
        : "+f"(d[0]), "+f"(d[1]), "+f"(d[2]), "+f"(d[3])
        : "r"(a[0]), "r"(a[1]), "r"(a[2]), "r"(a[3]), "r"(b[0]), "r"(b[1]));
}
// 3xTF32 split: x -> hi (tf32) + lo (tf32 of residual)
__device__ __forceinline__ void split_tf32(uint32_t x, uint32_t& hi, uint32_t& lo) {
    float f = __uint_as_float(x);
    uint32_t h;
    asm("cvt.rna.tf32.f32 %0, %1;" : "=r"(h) : "f"(f));
    float r = f - __uint_as_float(h);
    asm("cvt.rna.tf32.f32 %0, %1;" : "=r"(lo) : "f"(r));
    hi = h;
}

// ---------------------------------------------------------------------------
// 3xTF32 mma.sync GEMM: C[M,N] = act(A[M,K] @ BT^T + bias), fp32-accurate.
// A row-major [M,K]; BT row-major [N,K] (pre-transposed weights).
// Block 128x128, 8 warps (2x4), warp tile 64x32, K chunks of 32, cp.async x2.
// ---------------------------------------------------------------------------
template <int N, int K, bool RELU>
__global__ __launch_bounds__(256, 2) void mma_gemm(
    const float* __restrict__ A, const float* __restrict__ BT,
    const float* __restrict__ bias, float* __restrict__ C)
{
    constexpr int NC = K / 32;          // K chunks
    constexpr int PAD = 36;             // floats per smem row (conflict-free)
    constexpr int TILEB = 128 * PAD * 4;  // bytes per tile stage

    extern __shared__ float sh[];
    const uint32_t sb = smem_u32(sh);
    const uint32_t asB[2] = { sb, sb + TILEB };
    const uint32_t bsB[2] = { sb + 2 * TILEB, sb + 3 * TILEB };

    const int t = threadIdx.x;
    const int lane = t & 31, wid = t >> 5;
    const int wr = wid >> 2;            // 0..1 (64 rows)
    const int wc = wid & 3;             // 0..3 (32 cols)
    const int row0 = blockIdx.y * 128;
    const int col0 = blockIdx.x * 128;

    float acc[4][4][4];
#pragma unroll
    for (int i = 0; i < 4; i++)
#pragma unroll
        for (int j = 0; j < 4; j++)
#pragma unroll
            for (int k = 0; k < 4; k++) acc[i][j][k] = 0.0f;

    // ---- cp.async mappings: thread t copies 4x16B for A and for B ----
    const int r8 = t >> 3;              // 0..31
    const int c4 = t & 7;               // 0..7
    const float* Asrc = A + (long)(row0 + r8) * K + c4 * 4;
    uint32_t aDstOff = (uint32_t)((r8 * PAD + c4 * 4) * 4);

    uint32_t bSz[4];
    const float* Bsrc[4];
#pragma unroll
    for (int j = 0; j < 4; j++) {
        int n = col0 + r8 + 32 * j;
        bSz[j] = (n < N) ? 16u : 0u;
        int ncl = (n < N) ? n : (N - 1);
        Bsrc[j] = BT + (long)ncl * K + c4 * 4;
    }

    // ---- ldmatrix lane address offsets (bytes, within a tile stage) ----
    const uint32_t aLm = (uint32_t)(((wr * 64 + (lane & 15)) * PAD) * 4 + (lane >> 4) * 16);
    const uint32_t bLm = (uint32_t)(((wc * 32 + (lane & 7)) * PAD) * 4 + ((lane >> 3) & 1) * 16);

    // prologue: chunk 0 into buf 0
#pragma unroll
    for (int j = 0; j < 4; j++)
        cpa16(asB[0] + aDstOff + (uint32_t)(j * 32 * PAD * 4), Asrc + (long)j * 32 * K, 16u);
#pragma unroll
    for (int j = 0; j < 4; j++)
        cpa16(bsB[0] + aDstOff + (uint32_t)(j * 32 * PAD * 4), Bsrc[j], bSz[j]);
    cpa_commit();

    for (int c = 0; c < NC; c++) {
        const int buf = c & 1;
        if (c + 1 < NC) {
            const int nb = buf ^ 1;
            const long ko = (long)(c + 1) * 32;
#pragma unroll
            for (int j = 0; j < 4; j++)
                cpa16(asB[nb] + aDstOff + (uint32_t)(j * 32 * PAD * 4),
                      Asrc + (long)j * 32 * K + ko, 16u);
#pragma unroll
            for (int j = 0; j < 4; j++)
                cpa16(bsB[nb] + aDstOff + (uint32_t)(j * 32 * PAD * 4),
                      Bsrc[j] + ko, bSz[j]);
            cpa_commit();
            cpa_wait<1>();
        } else {
            cpa_wait<0>();
        }
        __syncthreads();

        const uint32_t aB = asB[buf] + aLm;
        const uint32_t bB = bsB[buf] + bLm;
#pragma unroll
        for (int kk = 0; kk < 4; kk++) {
            // B fragments: load + split once per kk
            uint32_t bh[4][2], bl[4][2];
#pragma unroll
            for (int nt = 0; nt < 4; nt++) {
                uint32_t bt[2];
                ldsm2(bt, bB + (uint32_t)(nt * 8 * PAD * 4 + kk * 32));
                split_tf32(bt[0], bh[nt][0], bl[nt][0]);
                split_tf32(bt[1], bh[nt][1], bl[nt][1]);
            }
            // A fragments: per mt, split, 3 MMAs per nt
#pragma unroll
            for (int mt = 0; mt < 4; mt++) {
                uint32_t at[4], ah[4], al[4];
                ldsm4(at, aB + (uint32_t)(mt * 16 * PAD * 4 + kk * 32));
#pragma unroll
                for (int q = 0; q < 4; q++) split_tf32(at[q], ah[q], al[q]);
#pragma unroll
                for (int nt = 0; nt < 4; nt++) {
                    mma_tf32(acc[mt][nt], ah, bh[nt]);
                    mma_tf32(acc[mt][nt], al, bh[nt]);
                    mma_tf32(acc[mt][nt], ah, bl[nt]);
                }
            }
        }
        __syncthreads();
    }

    // ---- epilogue: bias + relu, float2 stores ----
    const int rbase = row0 + wr * 64 + (lane >> 2);
    const int cbase = col0 + wc * 32 + (lane & 3) * 2;
#pragma unroll
    for (int nt = 0; nt < 4; nt++) {
        const int cc = cbase + nt * 8;
        if (cc < N) {
            const float bx = bias[cc], by = bias[cc + 1];
#pragma unroll
            for (int mt = 0; mt < 4; mt++) {
                const int r = rbase + mt * 16;
                float2 v0 = make_float2(acc[mt][nt][0] + bx, acc[mt][nt][1] + by);
                float2 v1 = make_float2(acc[mt][nt][2] + bx, acc[mt][nt][3] + by);
                if (RELU) {
                    v0.x = fmaxf(v0.x, 0.f); v0.y = fmaxf(v0.y, 0.f);
                    v1.x = fmaxf(v1.x, 0.f); v1.y = fmaxf(v1.y, 0.f);
                }
                *(float2*)&C[(long)r * N + cc] = v0;
                *(float2*)&C[(long)(r + 8) * N + cc] = v1;
            }
        }
    }
}

// ---------------------------------------------------------------------------
// Weight transpose: W[R,C] -> WT[C,R]
// ---------------------------------------------------------------------------
__global__ void transpose_k(const float* __restrict__ W, float* __restrict__ WT,
                            int R, int C) {
    __shared__ float tb[32][33];
    int c = blockIdx.x * 32 + threadIdx.x;
    int r0 = blockIdx.y * 32;
    for (int j = threadIdx.y; j < 32; j += 8)
        tb[j][threadIdx.x] = W[(r0 + j) * C + c];
    __syncthreads();
    int cOut = r0 + threadIdx.x;
    int roBase = blockIdx.x * 32;
    for (int j = threadIdx.y; j < 32; j += 8)
        WT[(roBase + j) * R + cOut] = tb[threadIdx.x][j];
}

// ---------------------------------------------------------------------------
__global__ void cls_kernel(const float* __restrict__ ab, int* __restrict__ cls) {
    int i = blockIdx.x * 256 + threadIdx.x;
    if (i >= NPIX) return;
    float bv = ab[i * PDIM];
    int best = 0;
#pragma unroll
    for (int p = 1; p < PDIM; p++) {
        float v = ab[i * PDIM + p];
        if (v > bv) { bv = v; best = p; }
    }
    cls[i] = best;
}

// ---------------------------------------------------------------------------
// Per-class masked online-softmax partials.
// ---------------------------------------------------------------------------
__global__ __launch_bounds__(256) void endmember_part(
    const float* __restrict__ logits, const float* __restrict__ Y,
    const int* __restrict__ cls)
{
    const int f0 = blockIdx.x * 8;
    const int sp = blockIdx.y;
    const int t = threadIdx.x;
    const int fi = t & 7, g = t >> 3;
    const int f = f0 + fi;
    constexpr int CH = NPIX / NSPLIT;

    float m[PDIM], s[PDIM], sy[PDIM];
#pragma unroll
    for (int p = 0; p < PDIM; p++) { m[p] = -FLT_MAX; s[p] = 0.f; sy[p] = 0.f; }

    const int nEnd = (sp + 1) * CH;
    for (int n = sp * CH + g; n < nEnd; n += 32) {
        const int c = cls[n];
        const float l = logits[n * FDIM + f];
        const float y = Y[n * FDIM + f];
        float mc = m[0], sc = s[0], syc = sy[0];
#pragma unroll
        for (int p = 1; p < PDIM; p++) {
            bool e = (c == p);
            mc = e ? m[p] : mc; sc = e ? s[p] : sc; syc = e ? sy[p] : syc;
        }
        float mn  = fmaxf(mc, l);
        float sca = __expf(mc - mn);
        float ea  = __expf(l - mn);
        float sn  = sc * sca + ea;
        float syn = syc * sca + ea * y;
#pragma unroll
        for (int p = 0; p < PDIM; p++) {
            bool e = (c == p);
            m[p] = e ? mn : m[p]; s[p] = e ? sn : s[p]; sy[p] = e ? syn : sy[p];
        }
    }

    __shared__ float sm[PDIM][256], ss[PDIM][256], ssy[PDIM][256];
#pragma unroll
    for (int p = 0; p < PDIM; p++) { sm[p][t] = m[p]; ss[p][t] = s[p]; ssy[p][t] = sy[p]; }
    __syncthreads();

    for (int off = 16; off > 0; off >>= 1) {
        if (g < off) {
            const int o = t + off * 8;
#pragma unroll
            for (int p = 0; p < PDIM; p++) {
                float mA = sm[p][t], sA = ss[p][t], syA = ssy[p][t];
                float mB = sm[p][o], sB = ss[p][o], syB = ssy[p][o];
                float mx = fmaxf(mA, mB);
                float eA = __expf(mA - mx);
                float eB = __expf(mB - mx);
                sm[p][t]  = mx;
                ss[p][t]  = sA * eA + sB * eB;
                ssy[p][t] = syA * eA + syB * eB;
            }
        }
        __syncthreads();
    }
    if (g == 0) {
#pragma unroll
        for (int p = 0; p < PDIM; p++) {
            g_part[sp][p][0][f] = sm[p][t];
            g_part[sp][p][1][f] = ss[p][t];
            g_part[sp][p][2][f] = ssy[p][t];
        }
    }
}

__global__ void endmember_combine(float* __restrict__ Mo) {
    int f = blockIdx.x * 32 + threadIdx.x;
    if (f >= FDIM) return;
#pragma unroll
    for (int p = 0; p < PDIM; p++) {
        float m = -FLT_MAX, s = 0.f, sy = 0.f;
        for (int sp = 0; sp < NSPLIT; sp++) {
            float m2 = g_part[sp][p][0][f];
            float s2 = g_part[sp][p][1][f];
            float sy2 = g_part[sp][p][2][f];
            float mx = fmaxf(m, m2);
            float e1 = __expf(m - mx), e2 = __expf(m2 - mx);
            s  = s * e1 + s2 * e2;
            sy = sy * e1 + sy2 * e2;
            m = mx;
        }
        Mo[p * FDIM + f] = (s > 0.f) ? (sy / s) : 0.0f;
    }
}

// ---------------------------------------------------------------------------
__global__ __launch_bounds__(256) void yhat_kernel(
    const float* __restrict__ ab, const float* __restrict__ M,
    float* __restrict__ out)
{
    __shared__ float sM[PDIM * FDIM];
    for (int i = threadIdx.x; i < PDIM * FDIM; i += 256) sM[i] = M[i];
    __syncthreads();
    long idx = (long)blockIdx.x * 256 + threadIdx.x;
    if (idx >= (long)NPIX * FDIM) return;
    int n = (int)(idx / FDIM);
    int f = (int)(idx % FDIM);
    const float* a = ab + (long)n * PDIM;
    float acc = 0.f;
#pragma unroll
    for (int p = 0; p < PDIM; p++) acc += a[p] * sM[p * FDIM + f];
    out[idx] = acc;
}

// ---------------------------------------------------------------------------
extern "C" void kernel_launch(void* const* d_in, const int* in_sizes, int n_in,
                              void* d_out, int out_size)
{
    const float* ab = (const float*)d_in[0];
    const float* Y  = (const float*)d_in[1];
    const float* W1 = (const float*)d_in[2];
    const float* b1 = (const float*)d_in[3];
    const float* W2 = (const float*)d_in[4];
    const float* b2 = (const float*)d_in[5];
    const float* W3 = (const float*)d_in[6];
    const float* b3 = (const float*)d_in[7];
    float* out = (float*)d_out;

    float *h1, *h2, *lg, *M, *w1t, *w2t, *w3t;
    int* cls;
    cudaGetSymbolAddress((void**)&h1,  g_h1);
    cudaGetSymbolAddress((void**)&h2,  g_h2);
    cudaGetSymbolAddress((void**)&lg,  g_logits);
    cudaGetSymbolAddress((void**)&cls, g_cls);
    cudaGetSymbolAddress((void**)&M,   g_M);
    cudaGetSymbolAddress((void**)&w1t, g_W1T);
    cudaGetSymbolAddress((void**)&w2t, g_W2T);
    cudaGetSymbolAddress((void**)&w3t, g_W3T);

    constexpr int SMEM = 4 * 128 * 36 * 4;  // 73728 bytes
    cudaFuncSetAttribute(mma_gemm<HDIM, FDIM, true>,
                         cudaFuncAttributeMaxDynamicSharedMemorySize, SMEM);
    cudaFuncSetAttribute(mma_gemm<HDIM, HDIM, true>,
                         cudaFuncAttributeMaxDynamicSharedMemorySize, SMEM);
    cudaFuncSetAttribute(mma_gemm<FDIM, HDIM, false>,
                         cudaFuncAttributeMaxDynamicSharedMemorySize, SMEM);

    transpose_k<<<dim3(HDIM / 32, FDIM / 32), dim3(32, 8)>>>(W1, w1t, FDIM, HDIM);
    transpose_k<<<dim3(HDIM / 32, HDIM / 32), dim3(32, 8)>>>(W2, w2t, HDIM, HDIM);
    transpose_k<<<dim3(FDIM / 32, HDIM / 32), dim3(32, 8)>>>(W3, w3t, HDIM, FDIM);
    cls_kernel<<<NPIX / 256, 256>>>(ab, cls);

    mma_gemm<HDIM, FDIM, true><<<dim3(2, NPIX / 128), 256, SMEM>>>(Y,  w1t, b1, h1);
    mma_gemm<HDIM, HDIM, true><<<dim3(2, NPIX / 128), 256, SMEM>>>(h1, w2t, b2, h2);
    mma_gemm<FDIM, HDIM, false><<<dim3(2, NPIX / 128), 256, SMEM>>>(h2, w3t, b3, lg);

    endmember_part<<<dim3(FDIM / 8, NSPLIT), 256>>>(lg, Y, cls);
    endmember_combine<<<(FDIM + 31) / 32, 32>>>(M);

    yhat_kernel<<<(int)(((long)NPIX * FDIM + 255) / 256), 256>>>(ab, M, out);
}

// round 5
// speedup vs baseline: 2.2109x; 1.2850x over previous
#include <cuda_runtime.h>
#include <cuda_fp16.h>
#include <cstdint>
#include <float.h>

#define NPIX 65536
#define FDIM 224
#define PDIM 6
#define HDIM 256
#define NSPLIT 8

// ------------------------- static device scratch ---------------------------
__device__ __half g_Yh[NPIX * FDIM];
__device__ __half g_Yl[NPIX * FDIM];
__device__ __half g_h1h[NPIX * HDIM];
__device__ __half g_h1l[NPIX * HDIM];
__device__ __half g_h2h[NPIX * HDIM];
__device__ __half g_h2l[NPIX * HDIM];
__device__ float  g_logits[NPIX * FDIM];
__device__ int    g_cls[NPIX];
__device__ float  g_M[PDIM * FDIM];
__device__ __half g_W1Th[HDIM * FDIM];
__device__ __half g_W1Tl[HDIM * FDIM];
__device__ __half g_W2Th[HDIM * HDIM];
__device__ __half g_W2Tl[HDIM * HDIM];
__device__ __half g_W3Th[FDIM * HDIM];
__device__ __half g_W3Tl[FDIM * HDIM];
__device__ float  g_part[NSPLIT][PDIM][3][FDIM];

// ------------------------------ PTX helpers --------------------------------
__device__ __forceinline__ uint32_t smem_u32(const void* p) {
    uint32_t a;
    asm("{ .reg .u64 t; cvta.to.shared.u64 t, %1; cvt.u32.u64 %0, t; }"
        : "=r"(a) : "l"(p));
    return a;
}
__device__ __forceinline__ void cpa16(uint32_t dst, const void* src, uint32_t sz) {
    asm volatile("cp.async.cg.shared.global [%0], [%1], 16, %2;"
                 :: "r"(dst), "l"(src), "r"(sz) : "memory");
}
__device__ __forceinline__ void cpa_commit() {
    asm volatile("cp.async.commit_group;" ::: "memory");
}
template <int n> __device__ __forceinline__ void cpa_wait() {
    asm volatile("cp.async.wait_group %0;" :: "n"(n) : "memory");
}
__device__ __forceinline__ void ldsm4(uint32_t* r, uint32_t addr) {
    asm volatile("ldmatrix.sync.aligned.m8n8.x4.shared.b16 {%0,%1,%2,%3}, [%4];"
                 : "=r"(r[0]), "=r"(r[1]), "=r"(r[2]), "=r"(r[3]) : "r"(addr));
}
__device__ __forceinline__ void ldsm2(uint32_t* r, uint32_t addr) {
    asm volatile("ldmatrix.sync.aligned.m8n8.x2.shared.b16 {%0,%1}, [%2];"
                 : "=r"(r[0]), "=r"(r[1]) : "r"(addr));
}
__device__ __forceinline__ void mma_f16(float* d, const uint32_t* a, const uint32_t* b) {
    asm volatile(
        "mma.sync.aligned.m16n8k16.row.col.f32.f16.f16.f32 "
        "{%0,%1,%2,%3}, {%4,%5,%6,%7}, {%8,%9}, {%0,%1,%2,%3};"
        : "+f"(d[0]), "+f"(d[1]), "+f"(d[2]), "+f"(d[3])
        : "r"(a[0]), "r"(a[1]), "r"(a[2]), "r"(a[3]), "r"(b[0]), "r"(b[1]));
}
__device__ __forceinline__ void split_h(float v, __half& hi, __half& lo) {
    hi = __float2half_rn(v);
    lo = __float2half_rn(v - __half2float(hi));
}

// ---------------------------------------------------------------------------
// fp16x3 mma.sync GEMM: C = act(A @ BT^T + bias), fp32-accurate.
// Operands pre-split: A = Ah + Al, BT = Bh + Bl (all __half, K-contiguous).
// Block 128x128, 8 warps (2x4), warp tile 64x32, K chunks of 32, cp.async x2.
// SPLIT_OUT: write hi/lo half pair outputs (for chained layers), else fp32.
// ---------------------------------------------------------------------------
template <int N, int K, bool RELU, bool SPLIT_OUT>
__global__ __launch_bounds__(256, 2) void mma_gemm_f16(
    const __half* __restrict__ Ah, const __half* __restrict__ Al,
    const __half* __restrict__ Bh, const __half* __restrict__ Bl,
    const float* __restrict__ bias,
    float* __restrict__ Cf, __half* __restrict__ Ch, __half* __restrict__ Cl)
{
    constexpr int NC = K / 32;           // K chunks of 32 halves
    constexpr int ROWB = 80;             // bytes per smem row (32 halves + pad)
    constexpr int COMPB = 128 * ROWB;    // 10240 bytes per component tile
    constexpr int STAGEB = 4 * COMPB;    // Ah,Al,Bh,Bl

    extern __shared__ char sh[];
    const uint32_t sb = smem_u32(sh);

    const int t = threadIdx.x;
    const int lane = t & 31, wid = t >> 5;
    const int wr = wid >> 2;             // 0..1
    const int wc = wid & 3;              // 0..3
    const int row0 = blockIdx.y * 128;
    const int col0 = blockIdx.x * 128;

    float acc[4][4][4];
#pragma unroll
    for (int i = 0; i < 4; i++)
#pragma unroll
        for (int j = 0; j < 4; j++)
#pragma unroll
            for (int k = 0; k < 4; k++) acc[i][j][k] = 0.0f;

    // ---- cp.async mapping: thread t, shot j: row=(t>>2)+64j, group g=t&3 ----
    const int cr = t >> 2;               // 0..63
    const int g  = t & 3;                // 16B group (8 halves)
    const uint32_t dOff = (uint32_t)(cr * ROWB + g * 16);
    const uint32_t dOff2 = dOff + (uint32_t)(64 * ROWB);

    const __half* Ah0 = Ah + (long)(row0 + cr) * K + g * 8;
    const __half* Al0 = Al + (long)(row0 + cr) * K + g * 8;
    int bn1 = col0 + cr, bn2 = col0 + cr + 64;
    const uint32_t bs1 = (bn1 < N) ? 16u : 0u;
    const uint32_t bs2 = (bn2 < N) ? 16u : 0u;
    if (bn1 >= N) bn1 = N - 1;
    if (bn2 >= N) bn2 = N - 1;
    const __half* Bh1 = Bh + (long)bn1 * K + g * 8;
    const __half* Bh2 = Bh + (long)bn2 * K + g * 8;
    const __half* Bl1 = Bl + (long)bn1 * K + g * 8;
    const __half* Bl2 = Bl + (long)bn2 * K + g * 8;

    // ---- ldmatrix lane offsets (bytes within a component tile) ----
    const uint32_t aLm = (uint32_t)((wr * 64 + (lane & 15)) * ROWB + (lane >> 4) * 16);
    const uint32_t bLm = (uint32_t)((wc * 32 + (lane & 7)) * ROWB + ((lane >> 3) & 1) * 16);

    auto load_chunk = [&](int stage, int k0) {
        const uint32_t st = sb + (uint32_t)(stage * STAGEB);
        cpa16(st + dOff,              Ah0 + k0,            16u);
        cpa16(st + dOff2,             Ah0 + k0 + 64L * K,  16u);
        cpa16(st + COMPB + dOff,      Al0 + k0,            16u);
        cpa16(st + COMPB + dOff2,     Al0 + k0 + 64L * K,  16u);
        cpa16(st + 2 * COMPB + dOff,  Bh1 + k0,            bs1);
        cpa16(st + 2 * COMPB + dOff2, Bh2 + k0,            bs2);
        cpa16(st + 3 * COMPB + dOff,  Bl1 + k0,            bs1);
        cpa16(st + 3 * COMPB + dOff2, Bl2 + k0,            bs2);
        cpa_commit();
    };

    load_chunk(0, 0);

    for (int c = 0; c < NC; c++) {
        const int buf = c & 1;
        if (c + 1 < NC) {
            load_chunk(buf ^ 1, (c + 1) * 32);
            cpa_wait<1>();
        } else {
            cpa_wait<0>();
        }
        __syncthreads();

        const uint32_t st = sb + (uint32_t)(buf * STAGEB);
        const uint32_t aHB = st + aLm;
        const uint32_t aLB = st + COMPB + aLm;
        const uint32_t bHB = st + 2 * COMPB + bLm;
        const uint32_t bLB = st + 3 * COMPB + bLm;

#pragma unroll
        for (int kk = 0; kk < 2; kk++) {
            uint32_t bh[4][2], bl[4][2];
#pragma unroll
            for (int nt = 0; nt < 4; nt++) {
                const uint32_t o = (uint32_t)(nt * 8 * ROWB + kk * 32);
                ldsm2(bh[nt], bHB + o);
                ldsm2(bl[nt], bLB + o);
            }
#pragma unroll
            for (int mt = 0; mt < 4; mt++) {
                const uint32_t o = (uint32_t)(mt * 16 * ROWB + kk * 32);
                uint32_t ah[4], al[4];
                ldsm4(ah, aHB + o);
                ldsm4(al, aLB + o);
#pragma unroll
                for (int nt = 0; nt < 4; nt++) {
                    mma_f16(acc[mt][nt], ah, bh[nt]);
                    mma_f16(acc[mt][nt], al, bh[nt]);
                    mma_f16(acc[mt][nt], ah, bl[nt]);
                }
            }
        }
        __syncthreads();
    }

    // ---- epilogue ----
    const int rbase = row0 + wr * 64 + (lane >> 2);
    const int cbase = col0 + wc * 32 + (lane & 3) * 2;
#pragma unroll
    for (int nt = 0; nt < 4; nt++) {
        const int cc = cbase + nt * 8;
        if (cc < N) {
            const float bx = bias[cc], by = bias[cc + 1];
#pragma unroll
            for (int mt = 0; mt < 4; mt++) {
                const int r = rbase + mt * 16;
                float v[4];
                v[0] = acc[mt][nt][0] + bx; v[1] = acc[mt][nt][1] + by;
                v[2] = acc[mt][nt][2] + bx; v[3] = acc[mt][nt][3] + by;
                if (RELU) {
#pragma unroll
                    for (int q = 0; q < 4; q++) v[q] = fmaxf(v[q], 0.f);
                }
                if (SPLIT_OUT) {
                    __half h0, l0, h1x, l1, h2x, l2, h3, l3;
                    split_h(v[0], h0, l0); split_h(v[1], h1x, l1);
                    split_h(v[2], h2x, l2); split_h(v[3], h3, l3);
                    *(__half2*)&Ch[(long)r * N + cc]       = __halves2half2(h0, h1x);
                    *(__half2*)&Cl[(long)r * N + cc]       = __halves2half2(l0, l1);
                    *(__half2*)&Ch[(long)(r + 8) * N + cc] = __halves2half2(h2x, h3);
                    *(__half2*)&Cl[(long)(r + 8) * N + cc] = __halves2half2(l2, l3);
                } else {
                    *(float2*)&Cf[(long)r * N + cc]       = make_float2(v[0], v[1]);
                    *(float2*)&Cf[(long)(r + 8) * N + cc] = make_float2(v[2], v[3]);
                }
            }
        }
    }
}

// ---------------------------------------------------------------------------
// Split fp32 array -> (hi, lo) fp16 arrays. n multiple of 4.
// ---------------------------------------------------------------------------
__global__ __launch_bounds__(256) void split_kernel(
    const float* __restrict__ in, __half* __restrict__ hi, __half* __restrict__ lo,
    int n4)
{
    int i = blockIdx.x * 256 + threadIdx.x;
    if (i >= n4) return;
    float4 v = ((const float4*)in)[i];
    __half h0, l0, h1, l1, h2, l2, h3, l3;
    split_h(v.x, h0, l0); split_h(v.y, h1, l1);
    split_h(v.z, h2, l2); split_h(v.w, h3, l3);
    ((__half2*)hi)[i * 2]     = __halves2half2(h0, h1);
    ((__half2*)hi)[i * 2 + 1] = __halves2half2(h2, h3);
    ((__half2*)lo)[i * 2]     = __halves2half2(l0, l1);
    ((__half2*)lo)[i * 2 + 1] = __halves2half2(l2, l3);
}

// ---------------------------------------------------------------------------
// Transpose + split: W[R,C] fp32 -> WTh/WTl [C,R] fp16.
// ---------------------------------------------------------------------------
__global__ void transpose_split(const float* __restrict__ W,
                                __half* __restrict__ WTh, __half* __restrict__ WTl,
                                int R, int C) {
    __shared__ float tb[32][33];
    int c = blockIdx.x * 32 + threadIdx.x;
    int r0 = blockIdx.y * 32;
    for (int j = threadIdx.y; j < 32; j += 8)
        tb[j][threadIdx.x] = W[(r0 + j) * C + c];
    __syncthreads();
    int rOut = r0 + threadIdx.x;
    int cBase = blockIdx.x * 32;
    for (int j = threadIdx.y; j < 32; j += 8) {
        float v = tb[threadIdx.x][j];
        __half h, l;
        split_h(v, h, l);
        WTh[(long)(cBase + j) * R + rOut] = h;
        WTl[(long)(cBase + j) * R + rOut] = l;
    }
}

// ---------------------------------------------------------------------------
__global__ void cls_kernel(const float* __restrict__ ab, int* __restrict__ cls) {
    int i = blockIdx.x * 256 + threadIdx.x;
    if (i >= NPIX) return;
    float bv = ab[i * PDIM];
    int best = 0;
#pragma unroll
    for (int p = 1; p < PDIM; p++) {
        float v = ab[i * PDIM + p];
        if (v > bv) { bv = v; best = p; }
    }
    cls[i] = best;
}

// ---------------------------------------------------------------------------
// Per-class masked online-softmax partials.
// ---------------------------------------------------------------------------
__global__ __launch_bounds__(256) void endmember_part(
    const float* __restrict__ logits, const float* __restrict__ Y,
    const int* __restrict__ cls)
{
    const int f0 = blockIdx.x * 8;
    const int sp = blockIdx.y;
    const int t = threadIdx.x;
    const int fi = t & 7, g = t >> 3;
    const int f = f0 + fi;
    constexpr int CH = NPIX / NSPLIT;

    float m[PDIM], s[PDIM], sy[PDIM];
#pragma unroll
    for (int p = 0; p < PDIM; p++) { m[p] = -FLT_MAX; s[p] = 0.f; sy[p] = 0.f; }

    const int nEnd = (sp + 1) * CH;
    for (int n = sp * CH + g; n < nEnd; n += 32) {
        const int c = cls[n];
        const float l = logits[n * FDIM + f];
        const float y = Y[n * FDIM + f];
        float mc = m[0], sc = s[0], syc = sy[0];
#pragma unroll
        for (int p = 1; p < PDIM; p++) {
            bool e = (c == p);
            mc = e ? m[p] : mc; sc = e ? s[p] : sc; syc = e ? sy[p] : syc;
        }
        float mn  = fmaxf(mc, l);
        float sca = __expf(mc - mn);
        float ea  = __expf(l - mn);
        float sn  = sc * sca + ea;
        float syn = syc * sca + ea * y;
#pragma unroll
        for (int p = 0; p < PDIM; p++) {
            bool e = (c == p);
            m[p] = e ? mn : m[p]; s[p] = e ? sn : s[p]; sy[p] = e ? syn : sy[p];
        }
    }

    __shared__ float sm[PDIM][256], ss[PDIM][256], ssy[PDIM][256];
#pragma unroll
    for (int p = 0; p < PDIM; p++) { sm[p][t] = m[p]; ss[p][t] = s[p]; ssy[p][t] = sy[p]; }
    __syncthreads();

    for (int off = 16; off > 0; off >>= 1) {
        if (g < off) {
            const int o = t + off * 8;
#pragma unroll
            for (int p = 0; p < PDIM; p++) {
                float mA = sm[p][t], sA = ss[p][t], syA = ssy[p][t];
                float mB = sm[p][o], sB = ss[p][o], syB = ssy[p][o];
                float mx = fmaxf(mA, mB);
                float eA = __expf(mA - mx);
                float eB = __expf(mB - mx);
                sm[p][t]  = mx;
                ss[p][t]  = sA * eA + sB * eB;
                ssy[p][t] = syA * eA + syB * eB;
            }
        }
        __syncthreads();
    }
    if (g == 0) {
#pragma unroll
        for (int p = 0; p < PDIM; p++) {
            g_part[sp][p][0][f] = sm[p][t];
            g_part[sp][p][1][f] = ss[p][t];
            g_part[sp][p][2][f] = ssy[p][t];
        }
    }
}

__global__ void endmember_combine(float* __restrict__ Mo) {
    int f = blockIdx.x * 32 + threadIdx.x;
    if (f >= FDIM) return;
#pragma unroll
    for (int p = 0; p < PDIM; p++) {
        float m = -FLT_MAX, s = 0.f, sy = 0.f;
        for (int sp = 0; sp < NSPLIT; sp++) {
            float m2 = g_part[sp][p][0][f];
            float s2 = g_part[sp][p][1][f];
            float sy2 = g_part[sp][p][2][f];
            float mx = fmaxf(m, m2);
            float e1 = __expf(m - mx), e2 = __expf(m2 - mx);
            s  = s * e1 + s2 * e2;
            sy = sy * e1 + sy2 * e2;
            m = mx;
        }
        Mo[p * FDIM + f] = (s > 0.f) ? (sy / s) : 0.0f;
    }
}

// ---------------------------------------------------------------------------
__global__ __launch_bounds__(256) void yhat_kernel(
    const float* __restrict__ ab, const float* __restrict__ M,
    float* __restrict__ out)
{
    __shared__ float sM[PDIM * FDIM];
    for (int i = threadIdx.x; i < PDIM * FDIM; i += 256) sM[i] = M[i];
    __syncthreads();
    long idx = (long)blockIdx.x * 256 + threadIdx.x;
    if (idx >= (long)NPIX * FDIM) return;
    int n = (int)(idx / FDIM);
    int f = (int)(idx % FDIM);
    const float* a = ab + (long)n * PDIM;
    float acc = 0.f;
#pragma unroll
    for (int p = 0; p < PDIM; p++) acc += a[p] * sM[p * FDIM + f];
    out[idx] = acc;
}

// ---------------------------------------------------------------------------
extern "C" void kernel_launch(void* const* d_in, const int* in_sizes, int n_in,
                              void* d_out, int out_size)
{
    const float* ab = (const float*)d_in[0];
    const float* Y  = (const float*)d_in[1];
    const float* W1 = (const float*)d_in[2];
    const float* b1 = (const float*)d_in[3];
    const float* W2 = (const float*)d_in[4];
    const float* b2 = (const float*)d_in[5];
    const float* W3 = (const float*)d_in[6];
    const float* b3 = (const float*)d_in[7];
    float* out = (float*)d_out;

    __half *yh, *yl, *h1h, *h1l, *h2h, *h2l;
    __half *w1h, *w1l, *w2h, *w2l, *w3h, *w3l;
    float *lg, *M;
    int* cls;
    cudaGetSymbolAddress((void**)&yh,  g_Yh);
    cudaGetSymbolAddress((void**)&yl,  g_Yl);
    cudaGetSymbolAddress((void**)&h1h, g_h1h);
    cudaGetSymbolAddress((void**)&h1l, g_h1l);
    cudaGetSymbolAddress((void**)&h2h, g_h2h);
    cudaGetSymbolAddress((void**)&h2l, g_h2l);
    cudaGetSymbolAddress((void**)&w1h, g_W1Th);
    cudaGetSymbolAddress((void**)&w1l, g_W1Tl);
    cudaGetSymbolAddress((void**)&w2h, g_W2Th);
    cudaGetSymbolAddress((void**)&w2l, g_W2Tl);
    cudaGetSymbolAddress((void**)&w3h, g_W3Th);
    cudaGetSymbolAddress((void**)&w3l, g_W3Tl);
    cudaGetSymbolAddress((void**)&lg,  g_logits);
    cudaGetSymbolAddress((void**)&cls, g_cls);
    cudaGetSymbolAddress((void**)&M,   g_M);

    constexpr int SMEM = 2 * 4 * 128 * 80;  // 81920 bytes
    cudaFuncSetAttribute(mma_gemm_f16<HDIM, FDIM, true, true>,
                         cudaFuncAttributeMaxDynamicSharedMemorySize, SMEM);
    cudaFuncSetAttribute(mma_gemm_f16<HDIM, HDIM, true, true>,
                         cudaFuncAttributeMaxDynamicSharedMemorySize, SMEM);
    cudaFuncSetAttribute(mma_gemm_f16<FDIM, HDIM, false, false>,
                         cudaFuncAttributeMaxDynamicSharedMemorySize, SMEM);

    // prep: splits + transposes + class argmax
    split_kernel<<<(NPIX * FDIM / 4 + 255) / 256, 256>>>(Y, yh, yl, NPIX * FDIM / 4);
    transpose_split<<<dim3(HDIM / 32, FDIM / 32), dim3(32, 8)>>>(W1, w1h, w1l, FDIM, HDIM);
    transpose_split<<<dim3(HDIM / 32, HDIM / 32), dim3(32, 8)>>>(W2, w2h, w2l, HDIM, HDIM);
    transpose_split<<<dim3(FDIM / 32, HDIM / 32), dim3(32, 8)>>>(W3, w3h, w3l, HDIM, FDIM);
    cls_kernel<<<NPIX / 256, 256>>>(ab, cls);

    mma_gemm_f16<HDIM, FDIM, true, true><<<dim3(2, NPIX / 128), 256, SMEM>>>(
        yh, yl, w1h, w1l, b1, nullptr, h1h, h1l);
    mma_gemm_f16<HDIM, HDIM, true, true><<<dim3(2, NPIX / 128), 256, SMEM>>>(
        h1h, h1l, w2h, w2l, b2, nullptr, h2h, h2l);
    mma_gemm_f16<FDIM, HDIM, false, false><<<dim3(2, NPIX / 128), 256, SMEM>>>(
        h2h, h2l, w3h, w3l, b3, lg, nullptr, nullptr);

    endmember_part<<<dim3(FDIM / 8, NSPLIT), 256>>>(lg, Y, cls);
    endmember_combine<<<(FDIM + 31) / 32, 32>>>(M);

    yhat_kernel<<<(int)(((long)NPIX * FDIM + 255) / 256), 256>>>(ab, M, out);
}

// round 6
// speedup vs baseline: 2.5383x; 1.1481x over previous
#include <cuda_runtime.h>
#include <cuda_fp16.h>
#include <cstdint>
#include <float.h>

#define NPIX 65536
#define FDIM 224
#define PDIM 6
#define HDIM 256
#define NCHUNK 512          // pixel chunks for endmember/yhat (128 px each)

// ------------------------- static device scratch ---------------------------
__device__ __half g_Yh[NPIX * FDIM];
__device__ __half g_Yl[NPIX * FDIM];
__device__ __half g_h1h[NPIX * HDIM];
__device__ __half g_h1l[NPIX * HDIM];
__device__ __half g_h2h[NPIX * HDIM];
__device__ __half g_h2l[NPIX * HDIM];
__device__ float  g_logits[NPIX * FDIM];
__device__ int    g_cls[NPIX];
__device__ float  g_M[PDIM * FDIM];
__device__ __half g_W1Th[HDIM * FDIM];
__device__ __half g_W1Tl[HDIM * FDIM];
__device__ __half g_W2Th[HDIM * HDIM];
__device__ __half g_W2Tl[HDIM * HDIM];
__device__ __half g_W3Th[FDIM * HDIM];
__device__ __half g_W3Tl[FDIM * HDIM];
// per-chunk partials: [chunk][class][{m,s,sy}][FDIM]
__device__ float  g_part[NCHUNK * PDIM * 3 * FDIM];

// ------------------------------ PTX helpers --------------------------------
__device__ __forceinline__ uint32_t smem_u32(const void* p) {
    uint32_t a;
    asm("{ .reg .u64 t; cvta.to.shared.u64 t, %1; cvt.u32.u64 %0, t; }"
        : "=r"(a) : "l"(p));
    return a;
}
__device__ __forceinline__ void cpa16(uint32_t dst, const void* src, uint32_t sz) {
    asm volatile("cp.async.cg.shared.global [%0], [%1], 16, %2;"
                 :: "r"(dst), "l"(src), "r"(sz) : "memory");
}
__device__ __forceinline__ void cpa_commit() {
    asm volatile("cp.async.commit_group;" ::: "memory");
}
template <int n> __device__ __forceinline__ void cpa_wait() {
    asm volatile("cp.async.wait_group %0;" :: "n"(n) : "memory");
}
__device__ __forceinline__ void ldsm4(uint32_t* r, uint32_t addr) {
    asm volatile("ldmatrix.sync.aligned.m8n8.x4.shared.b16 {%0,%1,%2,%3}, [%4];"
                 : "=r"(r[0]), "=r"(r[1]), "=r"(r[2]), "=r"(r[3]) : "r"(addr));
}
__device__ __forceinline__ void mma_f16(float* d, const uint32_t* a, const uint32_t* b) {
    asm volatile(
        "mma.sync.aligned.m16n8k16.row.col.f32.f16.f16.f32 "
        "{%0,%1,%2,%3}, {%4,%5,%6,%7}, {%8,%9}, {%0,%1,%2,%3};"
        : "+f"(d[0]), "+f"(d[1]), "+f"(d[2]), "+f"(d[3])
        : "r"(a[0]), "r"(a[1]), "r"(a[2]), "r"(a[3]), "r"(b[0]), "r"(b[1]));
}
__device__ __forceinline__ void split_h(float v, __half& hi, __half& lo) {
    hi = __float2half_rn(v);
    lo = __float2half_rn(v - __half2float(hi));
}

// ---------------------------------------------------------------------------
// fp16x3 mma.sync GEMM: C = act(A @ BT^T + bias), fp32-accurate.
// Operands pre-split: A = Ah + Al, BT = Bh + Bl (all __half, K-contiguous).
// Block 128x128, 8 warps (2x4), warp tile 64x32, K chunks of 32, cp.async x2.
// ---------------------------------------------------------------------------
template <int N, int K, bool RELU, bool SPLIT_OUT>
__global__ __launch_bounds__(256, 2) void mma_gemm_f16(
    const __half* __restrict__ Ah, const __half* __restrict__ Al,
    const __half* __restrict__ Bh, const __half* __restrict__ Bl,
    const float* __restrict__ bias,
    float* __restrict__ Cf, __half* __restrict__ Ch, __half* __restrict__ Cl)
{
    constexpr int NC = K / 32;
    constexpr int ROWB = 80;             // bytes per smem row (32 halves + pad)
    constexpr int COMPB = 128 * ROWB;
    constexpr int STAGEB = 4 * COMPB;

    extern __shared__ char sh[];
    const uint32_t sb = smem_u32(sh);

    const int t = threadIdx.x;
    const int lane = t & 31, wid = t >> 5;
    const int wr = wid >> 2;
    const int wc = wid & 3;
    const int row0 = blockIdx.y * 128;
    const int col0 = blockIdx.x * 128;

    float acc[4][4][4];
#pragma unroll
    for (int i = 0; i < 4; i++)
#pragma unroll
        for (int j = 0; j < 4; j++)
#pragma unroll
            for (int k = 0; k < 4; k++) acc[i][j][k] = 0.0f;

    const int cr = t >> 2;
    const int g  = t & 3;
    const uint32_t dOff = (uint32_t)(cr * ROWB + g * 16);
    const uint32_t dOff2 = dOff + (uint32_t)(64 * ROWB);

    const __half* Ah0 = Ah + (long)(row0 + cr) * K + g * 8;
    const __half* Al0 = Al + (long)(row0 + cr) * K + g * 8;
    int bn1 = col0 + cr, bn2 = col0 + cr + 64;
    const uint32_t bs1 = (bn1 < N) ? 16u : 0u;
    const uint32_t bs2 = (bn2 < N) ? 16u : 0u;
    if (bn1 >= N) bn1 = N - 1;
    if (bn2 >= N) bn2 = N - 1;
    const __half* Bh1 = Bh + (long)bn1 * K + g * 8;
    const __half* Bh2 = Bh + (long)bn2 * K + g * 8;
    const __half* Bl1 = Bl + (long)bn1 * K + g * 8;
    const __half* Bl2 = Bl + (long)bn2 * K + g * 8;

    const uint32_t aLm = (uint32_t)((wr * 64 + (lane & 15)) * ROWB + (lane >> 4) * 16);
    // B x4: lanes 0-7 rows n0-7/k0-7, 8-15 n0-7/k8-15, 16-23 n8-15/k0-7, 24-31 n8-15/k8-15
    const uint32_t bLm = (uint32_t)((wc * 32 + (lane & 7) + ((lane >> 4) << 3)) * ROWB
                                    + ((lane >> 3) & 1) * 16);

    auto load_chunk = [&](int stage, int k0) {
        const uint32_t st = sb + (uint32_t)(stage * STAGEB);
        cpa16(st + dOff,              Ah0 + k0,            16u);
        cpa16(st + dOff2,             Ah0 + k0 + 64L * K,  16u);
        cpa16(st + COMPB + dOff,      Al0 + k0,            16u);
        cpa16(st + COMPB + dOff2,     Al0 + k0 + 64L * K,  16u);
        cpa16(st + 2 * COMPB + dOff,  Bh1 + k0,            bs1);
        cpa16(st + 2 * COMPB + dOff2, Bh2 + k0,            bs2);
        cpa16(st + 3 * COMPB + dOff,  Bl1 + k0,            bs1);
        cpa16(st + 3 * COMPB + dOff2, Bl2 + k0,            bs2);
        cpa_commit();
    };

    load_chunk(0, 0);

    for (int c = 0; c < NC; c++) {
        const int buf = c & 1;
        if (c + 1 < NC) {
            load_chunk(buf ^ 1, (c + 1) * 32);
            cpa_wait<1>();
        } else {
            cpa_wait<0>();
        }
        __syncthreads();

        const uint32_t st = sb + (uint32_t)(buf * STAGEB);
        const uint32_t aHB = st + aLm;
        const uint32_t aLB = st + COMPB + aLm;
        const uint32_t bHB = st + 2 * COMPB + bLm;
        const uint32_t bLB = st + 3 * COMPB + bLm;

#pragma unroll
        for (int kk = 0; kk < 2; kk++) {
            uint32_t bh[4][2], bl[4][2];
#pragma unroll
            for (int pr = 0; pr < 2; pr++) {
                const uint32_t o = (uint32_t)(pr * 16 * ROWB + kk * 32);
                uint32_t r4[4];
                ldsm4(r4, bHB + o);
                bh[pr * 2][0] = r4[0]; bh[pr * 2][1] = r4[1];
                bh[pr * 2 + 1][0] = r4[2]; bh[pr * 2 + 1][1] = r4[3];
                ldsm4(r4, bLB + o);
                bl[pr * 2][0] = r4[0]; bl[pr * 2][1] = r4[1];
                bl[pr * 2 + 1][0] = r4[2]; bl[pr * 2 + 1][1] = r4[3];
            }
#pragma unroll
            for (int mt = 0; mt < 4; mt++) {
                const uint32_t o = (uint32_t)(mt * 16 * ROWB + kk * 32);
                uint32_t ah[4], al[4];
                ldsm4(ah, aHB + o);
                ldsm4(al, aLB + o);
#pragma unroll
                for (int nt = 0; nt < 4; nt++) mma_f16(acc[mt][nt], ah, bh[nt]);
#pragma unroll
                for (int nt = 0; nt < 4; nt++) mma_f16(acc[mt][nt], al, bh[nt]);
#pragma unroll
                for (int nt = 0; nt < 4; nt++) mma_f16(acc[mt][nt], ah, bl[nt]);
            }
        }
        __syncthreads();
    }

    // ---- epilogue ----
    const int rbase = row0 + wr * 64 + (lane >> 2);
    const int cbase = col0 + wc * 32 + (lane & 3) * 2;
#pragma unroll
    for (int nt = 0; nt < 4; nt++) {
        const int cc = cbase + nt * 8;
        if (cc < N) {
            const float bx = bias[cc], by = bias[cc + 1];
#pragma unroll
            for (int mt = 0; mt < 4; mt++) {
                const int r = rbase + mt * 16;
                float v[4];
                v[0] = acc[mt][nt][0] + bx; v[1] = acc[mt][nt][1] + by;
                v[2] = acc[mt][nt][2] + bx; v[3] = acc[mt][nt][3] + by;
                if (RELU) {
#pragma unroll
                    for (int q = 0; q < 4; q++) v[q] = fmaxf(v[q], 0.f);
                }
                if (SPLIT_OUT) {
                    __half h0, l0, h1x, l1, h2x, l2, h3, l3;
                    split_h(v[0], h0, l0); split_h(v[1], h1x, l1);
                    split_h(v[2], h2x, l2); split_h(v[3], h3, l3);
                    *(__half2*)&Ch[(long)r * N + cc]       = __halves2half2(h0, h1x);
                    *(__half2*)&Cl[(long)r * N + cc]       = __halves2half2(l0, l1);
                    *(__half2*)&Ch[(long)(r + 8) * N + cc] = __halves2half2(h2x, h3);
                    *(__half2*)&Cl[(long)(r + 8) * N + cc] = __halves2half2(l2, l3);
                } else {
                    *(float2*)&Cf[(long)r * N + cc]       = make_float2(v[0], v[1]);
                    *(float2*)&Cf[(long)(r + 8) * N + cc] = make_float2(v[2], v[3]);
                }
            }
        }
    }
}

// ---------------------------------------------------------------------------
// Split fp32 array -> (hi, lo) fp16 arrays. n multiple of 4.
// ---------------------------------------------------------------------------
__global__ __launch_bounds__(256) void split_kernel(
    const float* __restrict__ in, __half* __restrict__ hi, __half* __restrict__ lo,
    int n4)
{
    int i = blockIdx.x * 256 + threadIdx.x;
    if (i >= n4) return;
    float4 v = ((const float4*)in)[i];
    __half h0, l0, h1, l1, h2, l2, h3, l3;
    split_h(v.x, h0, l0); split_h(v.y, h1, l1);
    split_h(v.z, h2, l2); split_h(v.w, h3, l3);
    ((__half2*)hi)[i * 2]     = __halves2half2(h0, h1);
    ((__half2*)hi)[i * 2 + 1] = __halves2half2(h2, h3);
    ((__half2*)lo)[i * 2]     = __halves2half2(l0, l1);
    ((__half2*)lo)[i * 2 + 1] = __halves2half2(l2, l3);
}

// ---------------------------------------------------------------------------
// Fused transpose+split for all 3 weight matrices. grid (8,8,3), block (32,8).
// ---------------------------------------------------------------------------
__global__ void transpose_split_all(
    const float* __restrict__ W1, __half* __restrict__ T1h, __half* __restrict__ T1l,
    const float* __restrict__ W2, __half* __restrict__ T2h, __half* __restrict__ T2l,
    const float* __restrict__ W3, __half* __restrict__ T3h, __half* __restrict__ T3l)
{
    const float* W; __half* Th; __half* Tl; int R, C;
    if (blockIdx.z == 0)      { W = W1; Th = T1h; Tl = T1l; R = FDIM; C = HDIM; }
    else if (blockIdx.z == 1) { W = W2; Th = T2h; Tl = T2l; R = HDIM; C = HDIM; }
    else                      { W = W3; Th = T3h; Tl = T3l; R = HDIM; C = FDIM; }
    if ((int)blockIdx.x * 32 >= C || (int)blockIdx.y * 32 >= R) return;

    __shared__ float tb[32][33];
    int c = blockIdx.x * 32 + threadIdx.x;
    int r0 = blockIdx.y * 32;
    for (int j = threadIdx.y; j < 32; j += 8)
        tb[j][threadIdx.x] = W[(r0 + j) * C + c];
    __syncthreads();
    int rOut = r0 + threadIdx.x;
    int cBase = blockIdx.x * 32;
    for (int j = threadIdx.y; j < 32; j += 8) {
        float v = tb[threadIdx.x][j];
        __half h, l;
        split_h(v, h, l);
        Th[(long)(cBase + j) * R + rOut] = h;
        Tl[(long)(cBase + j) * R + rOut] = l;
    }
}

// ---------------------------------------------------------------------------
// argmax over P=6 per pixel, pixel-pair vectorized (12 floats = 3 float4).
// ---------------------------------------------------------------------------
__global__ __launch_bounds__(256) void cls_kernel2(
    const float* __restrict__ ab, int* __restrict__ cls)
{
    int i = blockIdx.x * 256 + threadIdx.x;   // pair index
    if (i >= NPIX / 2) return;
    const float4* p = (const float4*)(ab + (long)i * 12);
    float4 v0 = p[0], v1 = p[1], v2 = p[2];
    float a[6] = { v0.x, v0.y, v0.z, v0.w, v1.x, v1.y };
    float b[6] = { v1.z, v1.w, v2.x, v2.y, v2.z, v2.w };
    int ba = 0, bb = 0;
    float ma = a[0], mb = b[0];
#pragma unroll
    for (int q = 1; q < 6; q++) {
        if (a[q] > ma) { ma = a[q]; ba = q; }
        if (b[q] > mb) { mb = b[q]; bb = q; }
    }
    cls[i * 2] = ba;
    cls[i * 2 + 1] = bb;
}

// ---------------------------------------------------------------------------
// Endmember partials: thread <-> feature mapping, fully coalesced rows.
// grid NCHUNK blocks x 224 threads; each block: 128 consecutive pixels.
// ---------------------------------------------------------------------------
__global__ __launch_bounds__(224) void endmember_part2(
    const float* __restrict__ logits, const float* __restrict__ Y,
    const int* __restrict__ cls)
{
    const int blk = blockIdx.x;
    const int t = threadIdx.x;              // feature
    const int n0 = blk * (NPIX / NCHUNK);   // 128 pixels per chunk

    __shared__ int scls[NPIX / NCHUNK];
    for (int i = t; i < NPIX / NCHUNK; i += 224) scls[i] = cls[n0 + i];
    __syncthreads();

    float m[PDIM], s[PDIM], sy[PDIM];
#pragma unroll
    for (int p = 0; p < PDIM; p++) { m[p] = -FLT_MAX; s[p] = 0.f; sy[p] = 0.f; }

    for (int i = 0; i < NPIX / NCHUNK; i++) {
        const int c = scls[i];
        const long off = (long)(n0 + i) * FDIM + t;
        const float l = logits[off];
        const float y = Y[off];
        float mc = m[0], sc = s[0], syc = sy[0];
#pragma unroll
        for (int p = 1; p < PDIM; p++) {
            bool e = (c == p);
            mc = e ? m[p] : mc; sc = e ? s[p] : sc; syc = e ? sy[p] : syc;
        }
        float mn  = fmaxf(mc, l);
        float sca = __expf(mc - mn);
        float ea  = __expf(l - mn);
        float sn  = sc * sca + ea;
        float syn = syc * sca + ea * y;
#pragma unroll
        for (int p = 0; p < PDIM; p++) {
            bool e = (c == p);
            m[p] = e ? mn : m[p]; s[p] = e ? sn : s[p]; sy[p] = e ? syn : sy[p];
        }
    }

#pragma unroll
    for (int p = 0; p < PDIM; p++) {
        long base = (((long)blk * PDIM + p) * 3) * FDIM + t;
        g_part[base]             = m[p];
        g_part[base + FDIM]      = s[p];
        g_part[base + 2 * FDIM]  = sy[p];
    }
}

// grid PDIM blocks x 224 threads
__global__ __launch_bounds__(224) void endmember_combine2(float* __restrict__ Mo) {
    const int p = blockIdx.x;
    const int f = threadIdx.x;
    float m = -FLT_MAX, s = 0.f, sy = 0.f;
    for (int b = 0; b < NCHUNK; b++) {
        long base = (((long)b * PDIM + p) * 3) * FDIM + f;
        float m2 = g_part[base];
        float s2 = g_part[base + FDIM];
        float sy2 = g_part[base + 2 * FDIM];
        float mx = fmaxf(m, m2);
        float e1 = __expf(m - mx), e2 = __expf(m2 - mx);
        s  = s * e1 + s2 * e2;
        sy = sy * e1 + sy2 * e2;
        m = mx;
    }
    Mo[p * FDIM + f] = (s > 0.f) ? (sy / s) : 0.0f;
}

// ---------------------------------------------------------------------------
// Y_hat: grid NCHUNK x 224 threads, smem-staged M and abundances, coalesced.
// ---------------------------------------------------------------------------
__global__ __launch_bounds__(224) void yhat_kernel2(
    const float* __restrict__ ab, const float* __restrict__ M,
    float* __restrict__ out)
{
    constexpr int CH = NPIX / NCHUNK;  // 128
    __shared__ float sM[PDIM * FDIM];
    __shared__ float sab[CH * PDIM];
    const int t = threadIdx.x;
    const int n0 = blockIdx.x * CH;
    for (int i = t; i < PDIM * FDIM; i += 224) sM[i] = M[i];
    for (int i = t; i < CH * PDIM; i += 224) sab[i] = ab[(long)n0 * PDIM + i];
    __syncthreads();

    for (int i = 0; i < CH; i++) {
        float acc = 0.f;
#pragma unroll
        for (int p = 0; p < PDIM; p++) acc += sab[i * PDIM + p] * sM[p * FDIM + t];
        out[(long)(n0 + i) * FDIM + t] = acc;
    }
}

// ---------------------------------------------------------------------------
extern "C" void kernel_launch(void* const* d_in, const int* in_sizes, int n_in,
                              void* d_out, int out_size)
{
    const float* ab = (const float*)d_in[0];
    const float* Y  = (const float*)d_in[1];
    const float* W1 = (const float*)d_in[2];
    const float* b1 = (const float*)d_in[3];
    const float* W2 = (const float*)d_in[4];
    const float* b2 = (const float*)d_in[5];
    const float* W3 = (const float*)d_in[6];
    const float* b3 = (const float*)d_in[7];
    float* out = (float*)d_out;

    __half *yh, *yl, *h1h, *h1l, *h2h, *h2l;
    __half *w1h, *w1l, *w2h, *w2l, *w3h, *w3l;
    float *lg, *M;
    int* cls;
    cudaGetSymbolAddress((void**)&yh,  g_Yh);
    cudaGetSymbolAddress((void**)&yl,  g_Yl);
    cudaGetSymbolAddress((void**)&h1h, g_h1h);
    cudaGetSymbolAddress((void**)&h1l, g_h1l);
    cudaGetSymbolAddress((void**)&h2h, g_h2h);
    cudaGetSymbolAddress((void**)&h2l, g_h2l);
    cudaGetSymbolAddress((void**)&w1h, g_W1Th);
    cudaGetSymbolAddress((void**)&w1l, g_W1Tl);
    cudaGetSymbolAddress((void**)&w2h, g_W2Th);
    cudaGetSymbolAddress((void**)&w2l, g_W2Tl);
    cudaGetSymbolAddress((void**)&w3h, g_W3Th);
    cudaGetSymbolAddress((void**)&w3l, g_W3Tl);
    cudaGetSymbolAddress((void**)&lg,  g_logits);
    cudaGetSymbolAddress((void**)&cls, g_cls);
    cudaGetSymbolAddress((void**)&M,   g_M);

    constexpr int SMEM = 2 * 4 * 128 * 80;  // 81920 bytes
    cudaFuncSetAttribute(mma_gemm_f16<HDIM, FDIM, true, true>,
                         cudaFuncAttributeMaxDynamicSharedMemorySize, SMEM);
    cudaFuncSetAttribute(mma_gemm_f16<HDIM, HDIM, true, true>,
                         cudaFuncAttributeMaxDynamicSharedMemorySize, SMEM);
    cudaFuncSetAttribute(mma_gemm_f16<FDIM, HDIM, false, false>,
                         cudaFuncAttributeMaxDynamicSharedMemorySize, SMEM);

    // prep
    split_kernel<<<(NPIX * FDIM / 4 + 255) / 256, 256>>>(Y, yh, yl, NPIX * FDIM / 4);
    transpose_split_all<<<dim3(8, 8, 3), dim3(32, 8)>>>(
        W1, w1h, w1l, W2, w2h, w2l, W3, w3h, w3l);
    cls_kernel2<<<(NPIX / 2 + 255) / 256, 256>>>(ab, cls);

    // GEMM chain
    mma_gemm_f16<HDIM, FDIM, true, true><<<dim3(2, NPIX / 128), 256, SMEM>>>(
        yh, yl, w1h, w1l, b1, nullptr, h1h, h1l);
    mma_gemm_f16<HDIM, HDIM, true, true><<<dim3(2, NPIX / 128), 256, SMEM>>>(
        h1h, h1l, w2h, w2l, b2, nullptr, h2h, h2l);
    mma_gemm_f16<FDIM, HDIM, false, false><<<dim3(2, NPIX / 128), 256, SMEM>>>(
        h2h, h2l, w3h, w3l, b3, lg, nullptr, nullptr);

    // masked per-class softmax endmembers
    endmember_part2<<<NCHUNK, 224>>>(lg, Y, cls);
    endmember_combine2<<<PDIM, 224>>>(M);

    // reconstruction
    yhat_kernel2<<<NCHUNK, 224>>>(ab, M, out);
}